// round 15
// baseline (speedup 1.0000x reference)
#include <cuda_runtime.h>
#include <math.h>

#define LLEN 65536
#define CS 32
#define WARMT 12
#define TPB 64                  /* 2 warps per block */
#define NBLOCKS 1024            /* 2048 warps; each runs 2 packed streams */
#define TILE_SZF 2336           /* 2080-float window, +4 pad per 32 */

typedef unsigned long long u64;

__device__ __forceinline__ u64 pack2(float lo, float hi) {
    u64 r; asm("mov.b64 %0, {%1, %2};" : "=l"(r) : "f"(lo), "f"(hi)); return r;
}
__device__ __forceinline__ void unpack2(u64 v, float& lo, float& hi) {
    asm("mov.b64 {%0, %1}, %2;" : "=f"(lo), "=f"(hi) : "l"(v));
}
__device__ __forceinline__ u64 fma2(u64 a, u64 b, u64 c) {
    u64 d; asm("fma.rn.f32x2 %0, %1, %2, %3;" : "=l"(d) : "l"(a), "l"(b), "l"(c)); return d;
}
__device__ __forceinline__ u64 add2(u64 a, u64 b) {
    u64 d; asm("add.rn.f32x2 %0, %1, %2;" : "=l"(d) : "l"(a), "l"(b)); return d;
}
__device__ __forceinline__ u64 sub2(u64 a, u64 b) {
    u64 d; asm("sub.rn.f32x2 %0, %1, %2;" : "=l"(d) : "l"(a), "l"(b)); return d;
}
__device__ __forceinline__ u64 mul2(u64 a, u64 b) {
    u64 d; asm("mul.rn.f32x2 %0, %1, %2;" : "=l"(d) : "l"(a), "l"(b)); return d;
}
__device__ __forceinline__ u64 tanh2_(u64 v) {
    float lo, hi; unpack2(v, lo, hi);
    float a, b;
    asm("tanh.approx.f32 %0, %1;" : "=f"(a) : "f"(lo));
    asm("tanh.approx.f32 %0, %1;" : "=f"(b) : "f"(hi));
    return pack2(a, b);
}

struct Cf2 {
    u64 pb0, pb1, pb2, pb3, pb4, pna1, pna2, pna3, pna4;   // fused pre
    u64 GR1, CRc, GZ1, CZc, HR, HZ, GN1, CNc, MH, MB;      // GRU
    u64 WOUT, BOUT;
    u64 qb0, qb1, qb2, qb3, qb4, qna1, qna2, qna3, qna4;   // fused post
    u64 HALF;
};

struct St2 { u64 p1, p2, p3, p4, h, q1, q2, q3, q4; };

__device__ __forceinline__ u64 filt4p(u64 x_, u64 b0, u64 b1, u64 b2, u64 b3, u64 b4,
                                      u64 na1, u64 na2, u64 na3, u64 na4,
                                      u64& s1, u64& s2, u64& s3, u64& s4) {
    u64 y = fma2(b0, x_, s1);
    s1 = fma2(na1, y, fma2(b1, x_, s2));
    s2 = fma2(na2, y, fma2(b2, x_, s3));
    s3 = fma2(na3, y, fma2(b3, x_, s4));
    s4 = fma2(na4, y, mul2(b4, x_));
    return y;
}

__device__ __forceinline__ void step_light2(u64 xi, const Cf2& c, St2& s) {
    u64 v = filt4p(xi, c.pb0, c.pb1, c.pb2, c.pb3, c.pb4,
                   c.pna1, c.pna2, c.pna3, c.pna4, s.p1, s.p2, s.p3, s.p4);
    u64 tr = fma2(s.h, c.HR, fma2(v, c.GR1, c.CRc));
    u64 tz = fma2(s.h, c.HZ, fma2(v, c.GZ1, c.CZc));
    u64 M2 = fma2(s.h, c.MH, c.MB);
    u64 C2 = add2(fma2(v, c.GN1, c.CNc), M2);
    u64 t_r = tanh2_(tr);
    u64 t_z = tanh2_(tz);
    u64 z   = fma2(c.HALF, t_z, c.HALF);
    u64 sg  = fma2(t_r, M2, C2);
    u64 n   = tanh2_(sg);
    u64 d   = sub2(s.h, n);
    s.h = fma2(z, d, n);
}

__device__ __forceinline__ u64 step_full2(u64 xi, const Cf2& c, St2& s) {
    step_light2(xi, c, s);
    u64 u = fma2(c.WOUT, s.h, c.BOUT);
    return filt4p(u, c.qb0, c.qb1, c.qb2, c.qb3, c.qb4,
                  c.qna1, c.qna2, c.qna3, c.qna4, s.q1, s.q2, s.q3, s.q4);
}

__global__ void __launch_bounds__(TPB, 7) preamp_kernel(
    const float* __restrict__ x,
    const float* __restrict__ knobs,
    const float* __restrict__ pre_c,
    const float* __restrict__ post_c,
    const float* __restrict__ w_ih,
    const float* __restrict__ w_hh,
    const float* __restrict__ b_ih,
    const float* __restrict__ b_hh,
    const float* __restrict__ w_out,
    const float* __restrict__ b_out,
    const float* __restrict__ kw1,
    const float* __restrict__ kb1,
    const float* __restrict__ kw2,
    const float* __restrict__ kb2,
    float* __restrict__ out)
{
    __shared__ __align__(16) float tile[2][TILE_SZF];

    const int lane = threadIdx.x & 31;
    const int wid  = threadIdx.x >> 5;
    const int W    = blockIdx.x * 2 + wid;   // warp 0..2047
    const int row  = W >> 5;                 // row 0..63
    const int kp   = W & 31;                 // pair of 1024-sample halves

    // ---- Knob MLP, distributed across lanes (single row) ----
    float gain, bias;
    {
        const int unit = lane & 15;
        const float kn = knobs[row];
        float hh = tanhf(fmaf(kn, kw1[unit], kb1[unit]));
        float p0a = hh * kw2[unit];
        float p1a = hh * kw2[16 + unit];
#pragma unroll
        for (int m = 8; m >= 1; m >>= 1) {
            p0a += __shfl_xor_sync(0xffffffffu, p0a, m);
            p1a += __shfl_xor_sync(0xffffffffu, p1a, m);
        }
        float acc0 = p0a + kb2[0];
        float acc1 = p1a + kb2[1];
        float p0 = 1.0f / (1.0f + expf(-acc0));
        float p1 = 1.0f / (1.0f + expf(-acc1));
        gain = expf(fmaf(p0, 4.0f, -2.0f));
        bias = p1 * 0.1f;
    }

    // ---- Fold + pack constants (both halves identical: same row) ----
    Cf2 c;
    {
        float b0a = pre_c[0], b1a = pre_c[1], b2a = pre_c[2], a1a = pre_c[3], a2a = pre_c[4];
        float b0b = pre_c[5], b1b = pre_c[6], b2b = pre_c[7], a1b = pre_c[8], a2b = pre_c[9];
        float v;
        v = b0a * b0b;                                      c.pb0 = pack2(v, v);
        v = fmaf(b0a, b1b, b1a * b0b);                      c.pb1 = pack2(v, v);
        v = fmaf(b0a, b2b, fmaf(b1a, b1b, b2a * b0b));      c.pb2 = pack2(v, v);
        v = fmaf(b1a, b2b, b2a * b1b);                      c.pb3 = pack2(v, v);
        v = b2a * b2b;                                      c.pb4 = pack2(v, v);
        v = -(a1a + a1b);                                   c.pna1 = pack2(v, v);
        v = -(a2a + fmaf(a1a, a1b, a2b));                   c.pna2 = pack2(v, v);
        v = -fmaf(a1a, a2b, a2a * a1b);                     c.pna3 = pack2(v, v);
        v = -(a2a * a2b);                                   c.pna4 = pack2(v, v);
    }
    {
        float b0a = post_c[0], b1a = post_c[1], b2a = post_c[2], a1a = post_c[3], a2a = post_c[4];
        float b0b = post_c[5], b1b = post_c[6], b2b = post_c[7], a1b = post_c[8], a2b = post_c[9];
        float v;
        v = b0a * b0b;                                      c.qb0 = pack2(v, v);
        v = fmaf(b0a, b1b, b1a * b0b);                      c.qb1 = pack2(v, v);
        v = fmaf(b0a, b2b, fmaf(b1a, b1b, b2a * b0b));      c.qb2 = pack2(v, v);
        v = fmaf(b1a, b2b, b2a * b1b);                      c.qb3 = pack2(v, v);
        v = b2a * b2b;                                      c.qb4 = pack2(v, v);
        v = -(a1a + a1b);                                   c.qna1 = pack2(v, v);
        v = -(a2a + fmaf(a1a, a1b, a2b));                   c.qna2 = pack2(v, v);
        v = -fmaf(a1a, a2b, a2a * a1b);                     c.qna3 = pack2(v, v);
        v = -(a2a * a2b);                                   c.qna4 = pack2(v, v);
    }
    {
        float wih_r = w_ih[0], wih_z = w_ih[1], wih_n = w_ih[2];
        float whh_r = w_hh[0], whh_z = w_hh[1], whh_n = w_hh[2];
        float cr = b_ih[0] + b_hh[0];
        float cz = b_ih[1] + b_hh[1];
        float v;
        v = 0.5f * wih_r * gain;          c.GR1 = pack2(v, v);
        v = 0.5f * fmaf(wih_r, bias, cr); c.CRc = pack2(v, v);
        v = 0.5f * wih_z * gain;          c.GZ1 = pack2(v, v);
        v = 0.5f * fmaf(wih_z, bias, cz); c.CZc = pack2(v, v);
        v = 0.5f * whh_r;                 c.HR  = pack2(v, v);
        v = 0.5f * whh_z;                 c.HZ  = pack2(v, v);
        v = wih_n * gain;                 c.GN1 = pack2(v, v);
        v = fmaf(wih_n, bias, b_ih[2]);   c.CNc = pack2(v, v);
        v = 0.5f * whh_n;                 c.MH  = pack2(v, v);
        v = 0.5f * b_hh[2];               c.MB  = pack2(v, v);
        v = w_out[0];                     c.WOUT = pack2(v, v);
        v = b_out[0];                     c.BOUT = pack2(v, v);
        c.HALF = pack2(0.5f, 0.5f);
    }

    St2 s;
    s.p1 = s.p2 = s.p3 = s.p4 = 0ull;
    s.h = 0ull;
    s.q1 = s.q2 = s.q3 = s.q4 = 0ull;

    // ============ Unified fast path ============
    // Window: global floats [kp*2048 - 32, kp*2048 + 2048) = 2080 floats (520 float4).
    // For kp==0, the first 8 float4 (floats [-32,0)) are skipped (never validly read;
    // lane-0 stream-A warmup reads garbage there and its state is reset below).
    const float* xr = x + (size_t)row * LLEN;
    const float4* xr4 = (const float4*)(xr + (kp * 2048 - 32));
    float* tl = tile[wid];
    float4* tl4 = reinterpret_cast<float4*>(tl);
#pragma unroll
    for (int rep = 0; rep < 16; rep++) {
        int i = rep * 32 + lane;
        if (kp != 0 || i >= 8)
            tl4[i + (i >> 3)] = __ldg(xr4 + i);   // padded loc4(i) = i + (i>>3)
    }
    if (lane < 8) {
        int i = 512 + lane;
        tl4[i + (i >> 3)] = __ldg(xr4 + i);
    }
    __syncwarp();

    // Stream A: window floats [32*lane+20, 32*lane+64)  (12 warm + 32 main)
    //   padded: warm f4 = 9*lane+5 (3 f4), main f4 = 9*lane+9 (8 f4, contiguous)
    // Stream B: +1024 window floats -> +288 padded f4.
    const float4* wA = reinterpret_cast<const float4*>(tl) + (9 * lane + 5);
    const float4* wB = wA + 288;
    const float4* mA = wA + 4;
    const float4* mB = mA + 288;

    // warmup light: k=0..3
    {
        float4 fa = wA[0], fb = wB[0];
        step_light2(pack2(fa.x, fb.x), c, s);
        step_light2(pack2(fa.y, fb.y), c, s);
        step_light2(pack2(fa.z, fb.z), c, s);
        step_light2(pack2(fa.w, fb.w), c, s);
    }
    // warmup full: k=4..11
#pragma unroll
    for (int j = 1; j < 3; j++) {
        float4 fa = wA[j], fb = wB[j];
        step_full2(pack2(fa.x, fb.x), c, s);
        step_full2(pack2(fa.y, fb.y), c, s);
        step_full2(pack2(fa.z, fb.z), c, s);
        step_full2(pack2(fa.w, fb.w), c, s);
    }

    // kp==0, lane 0: stream A starts at t=0 where the true state is exactly zero.
    // Its warmup consumed garbage; reset the lo (A) halves, keep hi (B).
    if (kp == 0 && lane == 0) {
        const u64 M = 0xFFFFFFFF00000000ull;
        s.p1 &= M; s.p2 &= M; s.p3 &= M; s.p4 &= M;
        s.h  &= M;
        s.q1 &= M; s.q2 &= M; s.q3 &= M; s.q4 &= M;
    }

    // main: k=12..43, outputs 0..31 per stream
    float4* ovA = (float4*)(out + (size_t)row * LLEN + (size_t)(kp * 2048) + (size_t)lane * CS);
    float4* ovB = ovA + 256;   // +1024 samples
#pragma unroll
    for (int j = 0; j < 8; j++) {
        float4 fa = mA[j], fb = mB[j];
        float4 oa, ob;
        u64 w;
        w = step_full2(pack2(fa.x, fb.x), c, s); unpack2(w, oa.x, ob.x);
        w = step_full2(pack2(fa.y, fb.y), c, s); unpack2(w, oa.y, ob.y);
        w = step_full2(pack2(fa.z, fb.z), c, s); unpack2(w, oa.z, ob.z);
        w = step_full2(pack2(fa.w, fb.w), c, s); unpack2(w, oa.w, ob.w);
        ovA[j] = oa;
        ovB[j] = ob;
    }
}

extern "C" void kernel_launch(void* const* d_in, const int* in_sizes, int n_in,
                              void* d_out, int out_size) {
    (void)in_sizes; (void)n_in; (void)out_size;
    preamp_kernel<<<NBLOCKS, TPB>>>(
        (const float*)d_in[0],  (const float*)d_in[1],  (const float*)d_in[2],
        (const float*)d_in[3],  (const float*)d_in[4],  (const float*)d_in[5],
        (const float*)d_in[6],  (const float*)d_in[7],  (const float*)d_in[8],
        (const float*)d_in[9],  (const float*)d_in[10], (const float*)d_in[11],
        (const float*)d_in[12], (const float*)d_in[13], (float*)d_out);
}

// round 16
// speedup vs baseline: 1.0368x; 1.0368x over previous
#include <cuda_runtime.h>
#include <math.h>

#define LLEN 65536
#define CS 32                   /* samples per chunk */
#define WARMT 12                /* warmup steps (must be mult of 4) */
#define TPB 64                  /* 2 warps per block */
#define NGROUPS 4096            /* 64 rows * 64 groups */
#define NBLOCKS (NGROUPS / 2)   /* 2048 */
#define TILE_SZF 1168           /* 1036 floats staged w/ +4 pad per 32 */

struct Cf {
    float pb0, pb1, pb2, pb3, pb4, pna1, pna2, pna3, pna4;   // fused pre (4th order)
    float GR1, CRc, GZ1, CZc, HR, HZ, GN1, CNc, MH, MB;      // GRU (gain/bias folded)
    float wout, bout;
    float qb0, qb1, qb2, qb3, qb4, qna1, qna2, qna3, qna4;   // fused post
};

struct F4 { float s1, s2, s3, s4; };

__device__ __forceinline__ float tanha_(float x) {
    float y; asm("tanh.approx.f32 %0, %1;" : "=f"(y) : "f"(x)); return y;
}

// 4th-order DF-II-transposed, 9 FMA
__device__ __forceinline__ float filt4(float x_, float b0, float b1, float b2,
                                       float b3, float b4, float na1, float na2,
                                       float na3, float na4, F4& s) {
    float y = fmaf(b0, x_, s.s1);
    s.s1 = fmaf(na1, y, fmaf(b1, x_, s.s2));
    s.s2 = fmaf(na2, y, fmaf(b2, x_, s.s3));
    s.s3 = fmaf(na3, y, fmaf(b3, x_, s.s4));
    s.s4 = fmaf(na4, y, b4 * x_);
    return y;
}

__device__ __forceinline__ float gru1(float v, const Cf& c, float h) {
    float tr = fmaf(h, c.HR, fmaf(v, c.GR1, c.CRc));
    float tz = fmaf(h, c.HZ, fmaf(v, c.GZ1, c.CZc));
    float M2 = fmaf(h, c.MH, c.MB);
    float C2 = fmaf(v, c.GN1, c.CNc) + M2;
    float t_r = tanha_(tr);
    float t_z = tanha_(tz);
    float z   = fmaf(0.5f, t_z, 0.5f);
    float sg  = fmaf(t_r, M2, C2);
    float n   = tanha_(sg);
    float d   = h - n;
    return fmaf(z, d, n);
}

// ---- Phase-blocked quad processing (bit-identical per-sample arithmetic) ----
__device__ __forceinline__ void quad_pre(const float4& f, const Cf& c, F4& sp, float* v) {
    v[0] = filt4(f.x, c.pb0, c.pb1, c.pb2, c.pb3, c.pb4, c.pna1, c.pna2, c.pna3, c.pna4, sp);
    v[1] = filt4(f.y, c.pb0, c.pb1, c.pb2, c.pb3, c.pb4, c.pna1, c.pna2, c.pna3, c.pna4, sp);
    v[2] = filt4(f.z, c.pb0, c.pb1, c.pb2, c.pb3, c.pb4, c.pna1, c.pna2, c.pna3, c.pna4, sp);
    v[3] = filt4(f.w, c.pb0, c.pb1, c.pb2, c.pb3, c.pb4, c.pna1, c.pna2, c.pna3, c.pna4, sp);
}
__device__ __forceinline__ void quad_gru(const float* v, const Cf& c, float& h, float* hh) {
    h = gru1(v[0], c, h); hh[0] = h;
    h = gru1(v[1], c, h); hh[1] = h;
    h = gru1(v[2], c, h); hh[2] = h;
    h = gru1(v[3], c, h); hh[3] = h;
}
__device__ __forceinline__ float4 quad_post(const float* hh, const Cf& c, F4& sq) {
    float4 o;
    o.x = filt4(fmaf(c.wout, hh[0], c.bout), c.qb0, c.qb1, c.qb2, c.qb3, c.qb4,
                c.qna1, c.qna2, c.qna3, c.qna4, sq);
    o.y = filt4(fmaf(c.wout, hh[1], c.bout), c.qb0, c.qb1, c.qb2, c.qb3, c.qb4,
                c.qna1, c.qna2, c.qna3, c.qna4, sq);
    o.z = filt4(fmaf(c.wout, hh[2], c.bout), c.qb0, c.qb1, c.qb2, c.qb3, c.qb4,
                c.qna1, c.qna2, c.qna3, c.qna4, sq);
    o.w = filt4(fmaf(c.wout, hh[3], c.bout), c.qb0, c.qb1, c.qb2, c.qb3, c.qb4,
                c.qna1, c.qna2, c.qna3, c.qna4, sq);
    return o;
}

__global__ void __launch_bounds__(TPB, 14) preamp_kernel(
    const float* __restrict__ x,
    const float* __restrict__ knobs,
    const float* __restrict__ pre_c,
    const float* __restrict__ post_c,
    const float* __restrict__ w_ih,
    const float* __restrict__ w_hh,
    const float* __restrict__ b_ih,
    const float* __restrict__ b_hh,
    const float* __restrict__ w_out,
    const float* __restrict__ b_out,
    const float* __restrict__ kw1,
    const float* __restrict__ kb1,
    const float* __restrict__ kw2,
    const float* __restrict__ kb2,
    float* __restrict__ out)
{
    __shared__ __align__(16) float tile[2][TILE_SZF];

    const int lane = threadIdx.x & 31;
    const int wid  = threadIdx.x >> 5;
    const int G    = blockIdx.x * 2 + wid;
    const int row  = G >> 6;
    const int gidx = G & 63;

    // ---- Knob MLP, distributed across lanes ----
    float gain, bias;
    {
        const int unit = lane & 15;
        const float kn = knobs[row];
        float hh = tanhf(fmaf(kn, kw1[unit], kb1[unit]));
        float p0a = hh * kw2[unit];
        float p1a = hh * kw2[16 + unit];
#pragma unroll
        for (int m = 8; m >= 1; m >>= 1) {
            p0a += __shfl_xor_sync(0xffffffffu, p0a, m);
            p1a += __shfl_xor_sync(0xffffffffu, p1a, m);
        }
        float acc0 = p0a + kb2[0];
        float acc1 = p1a + kb2[1];
        float p0 = 1.0f / (1.0f + expf(-acc0));
        float p1 = 1.0f / (1.0f + expf(-acc1));
        gain = expf(fmaf(p0, 4.0f, -2.0f));
        bias = p1 * 0.1f;
    }

    // ---- Fold constants ----
    Cf c;
    {
        float b0a = pre_c[0], b1a = pre_c[1], b2a = pre_c[2], a1a = pre_c[3], a2a = pre_c[4];
        float b0b = pre_c[5], b1b = pre_c[6], b2b = pre_c[7], a1b = pre_c[8], a2b = pre_c[9];
        c.pb0 = b0a * b0b;
        c.pb1 = fmaf(b0a, b1b, b1a * b0b);
        c.pb2 = fmaf(b0a, b2b, fmaf(b1a, b1b, b2a * b0b));
        c.pb3 = fmaf(b1a, b2b, b2a * b1b);
        c.pb4 = b2a * b2b;
        c.pna1 = -(a1a + a1b);
        c.pna2 = -(a2a + fmaf(a1a, a1b, a2b));
        c.pna3 = -fmaf(a1a, a2b, a2a * a1b);
        c.pna4 = -(a2a * a2b);
    }
    {
        float b0a = post_c[0], b1a = post_c[1], b2a = post_c[2], a1a = post_c[3], a2a = post_c[4];
        float b0b = post_c[5], b1b = post_c[6], b2b = post_c[7], a1b = post_c[8], a2b = post_c[9];
        c.qb0 = b0a * b0b;
        c.qb1 = fmaf(b0a, b1b, b1a * b0b);
        c.qb2 = fmaf(b0a, b2b, fmaf(b1a, b1b, b2a * b0b));
        c.qb3 = fmaf(b1a, b2b, b2a * b1b);
        c.qb4 = b2a * b2b;
        c.qna1 = -(a1a + a1b);
        c.qna2 = -(a2a + fmaf(a1a, a1b, a2b));
        c.qna3 = -fmaf(a1a, a2b, a2a * a1b);
        c.qna4 = -(a2a * a2b);
    }
    {
        float wih_r = w_ih[0], wih_z = w_ih[1], wih_n = w_ih[2];
        float whh_r = w_hh[0], whh_z = w_hh[1], whh_n = w_hh[2];
        float cr = b_ih[0] + b_hh[0];
        float cz = b_ih[1] + b_hh[1];
        c.GR1 = 0.5f * wih_r * gain; c.CRc = 0.5f * fmaf(wih_r, bias, cr);
        c.GZ1 = 0.5f * wih_z * gain; c.CZc = 0.5f * fmaf(wih_z, bias, cz);
        c.HR  = 0.5f * whh_r;        c.HZ  = 0.5f * whh_z;
        c.GN1 = wih_n * gain;        c.CNc = fmaf(wih_n, bias, b_ih[2]);
        c.MH  = 0.5f * whh_n;        c.MB  = 0.5f * b_hh[2];
        c.wout = w_out[0];           c.bout = b_out[0];
    }

    F4 sp = {0,0,0,0}, sq = {0,0,0,0};
    float h = 0.f;
    float v[4], hh[4];

    if (gidx != 0) {
        // ============ FAST PATH ============
        const int base = gidx * 1024 - WARMT;
        const float4* xr4 = (const float4*)(x + (size_t)row * LLEN + base);
        float4* tl4 = reinterpret_cast<float4*>(tile[wid]);
#pragma unroll
        for (int rep = 0; rep < 8; rep++) {
            int i = rep * 32 + lane;
            tl4[i + (i >> 3)] = __ldg(xr4 + i);
        }
        if (lane < 3) {
            int i = 256 + lane;
            tl4[i + (i >> 3)] = __ldg(xr4 + i);
        }
        __syncwarp();

        const float4* lw = reinterpret_cast<const float4*>(tile[wid] + 36 * lane);

        // warmup: 12 steps = 3 quads. Quad 0 is pre+GRU only (light);
        // quads 1-2 full (discard). Prefetch one quad ahead.
        float4 f_cur = lw[0];
        float4 f_nxt = lw[1];
        {   // light quad (k=0..3): no post
            quad_pre(f_cur, c, sp, v);
            quad_gru(v, c, h, hh);
        }
        f_cur = f_nxt; f_nxt = lw[2];
        {   // full warm quad 1
            quad_pre(f_cur, c, sp, v);
            quad_gru(v, c, h, hh);
            quad_post(hh, c, sq);
        }
        f_cur = f_nxt; f_nxt = lw[3];
        {   // full warm quad 2
            quad_pre(f_cur, c, sp, v);
            quad_gru(v, c, h, hh);
            quad_post(hh, c, sq);
        }

        const size_t t0 = (size_t)(gidx * 32 + lane) * CS;
        float4* ov = (float4*)(out + (size_t)row * LLEN + t0);

        // main part 1: j=3..7 (outputs 0..4)
#pragma unroll
        for (int j = 3; j < 8; j++) {
            f_cur = f_nxt;
            f_nxt = lw[(j + 1 < 8) ? (j + 1) : 9];   // skip pad slot 8
            quad_pre(f_cur, c, sp, v);
            quad_gru(v, c, h, hh);
            ov[j - 3] = quad_post(hh, c, sq);
        }
        // main part 2: j=9..11 (outputs 5..7)
#pragma unroll
        for (int j = 9; j < 12; j++) {
            f_cur = f_nxt;
            f_nxt = (j + 1 < 12) ? lw[j + 1] : f_cur;
            quad_pre(f_cur, c, sp, v);
            quad_gru(v, c, h, hh);
            ov[j - 4] = quad_post(hh, c, sq);
        }
    } else {
        // ============ SLOW PATH: first 32 chunks of each row ============
        const int t0 = lane * CS;
        const int s0 = (t0 > WARMT) ? (t0 - WARMT) : 0;
        const int f0 = (t0 > (WARMT - 4)) ? (t0 - (WARMT - 4)) : 0;
        const float4* xr4 = (const float4*)(x + (size_t)row * LLEN);

        for (int q = s0 / 4; q < f0 / 4; q++) {      // light quads
            float4 a = __ldg(xr4 + q);
            quad_pre(a, c, sp, v);
            quad_gru(v, c, h, hh);
        }
        for (int q = f0 / 4; q < t0 / 4; q++) {      // full warm quads
            float4 a = __ldg(xr4 + q);
            quad_pre(a, c, sp, v);
            quad_gru(v, c, h, hh);
            quad_post(hh, c, sq);
        }
        float4* ov = (float4*)(out + (size_t)row * LLEN + t0);
        for (int q = t0 / 4, j = 0; q < (t0 + CS) / 4; q++, j++) {
            float4 a = __ldg(xr4 + q);
            quad_pre(a, c, sp, v);
            quad_gru(v, c, h, hh);
            ov[j] = quad_post(hh, c, sq);
        }
    }
}

extern "C" void kernel_launch(void* const* d_in, const int* in_sizes, int n_in,
                              void* d_out, int out_size) {
    (void)in_sizes; (void)n_in; (void)out_size;
    preamp_kernel<<<NBLOCKS, TPB>>>(
        (const float*)d_in[0],  (const float*)d_in[1],  (const float*)d_in[2],
        (const float*)d_in[3],  (const float*)d_in[4],  (const float*)d_in[5],
        (const float*)d_in[6],  (const float*)d_in[7],  (const float*)d_in[8],
        (const float*)d_in[9],  (const float*)d_in[10], (const float*)d_in[11],
        (const float*)d_in[12], (const float*)d_in[13], (float*)d_out);
}